// round 2
// baseline (speedup 1.0000x reference)
#include <cuda_runtime.h>

#define N_NODES 100000
#define N_EDGES 3200000
#define D_IN 83
#define XP 96          // padded x row stride (384B = 3 x 128B lines)
#define D_HID 1024
#define NC 25
#define ZP 32          // padded z row stride (128B = 1 line)

// ---------------- scratch (device globals; no allocation allowed) ----------
__device__ float g_x[(size_t)N_NODES * XP];    // conv output, padded
__device__ float g_ax[(size_t)N_NODES * XP];   // A @ x
__device__ float g_h[(size_t)N_NODES * D_HID]; // hidden layer (409.6 MB)
__device__ float g_z[(size_t)N_NODES * ZP];    // h @ W2, padded

typedef unsigned long long ull;

__device__ __forceinline__ ull dup2(float x) {
    ull r; asm("mov.b64 %0, {%1, %1};" : "=l"(r) : "f"(x)); return r;
}
__device__ __forceinline__ ull pack2(float lo, float hi) {
    ull r; asm("mov.b64 %0, {%1, %2};" : "=l"(r) : "f"(lo), "f"(hi)); return r;
}
__device__ __forceinline__ void unpack2(ull v, float& lo, float& hi) {
    asm("mov.b64 {%0, %1}, %2;" : "=f"(lo), "=f"(hi) : "l"(v));
}
__device__ __forceinline__ void fma2(ull& d, ull a, ull b) {
    asm("fma.rn.f32x2 %0, %1, %2, %0;" : "+l"(d) : "l"(a), "l"(b));
}
__device__ __forceinline__ ull add2(ull a, ull b) {
    ull r; asm("add.rn.f32x2 %0, %1, %2;" : "=l"(r) : "l"(a), "l"(b)); return r;
}

// ---------------- 1. conv1d(1->4,k5,p2) + channel-sum + relu ----------------
// sum_c conv(w_c) + b_c == conv(sum_c w_c) + sum_c b_c
__global__ void conv_relu_kernel(const float* __restrict__ feat,
                                 const float* __restrict__ conv_w,
                                 const float* __restrict__ conv_b) {
    __shared__ float srow[D_IN];
    __shared__ float sw[5];
    __shared__ float sb;
    int n = blockIdx.x;
    int t = threadIdx.x;  // 96 threads
    if (t < 5) sw[t] = conv_w[t] + conv_w[5 + t] + conv_w[10 + t] + conv_w[15 + t];
    if (t == 5) sb = conv_b[0] + conv_b[1] + conv_b[2] + conv_b[3];
    if (t < D_IN) srow[t] = feat[(size_t)n * D_IN + t];
    __syncthreads();
    float r = 0.f;
    if (t < D_IN) {
        float s = sb;
        #pragma unroll
        for (int k = 0; k < 5; k++) {
            int j = t + k - 2;
            if (j >= 0 && j < D_IN) s += srow[j] * sw[k];
        }
        r = fmaxf(s, 0.f);
    }
    g_x[(size_t)n * XP + t] = r;  // cols 83..95 get 0
}

// ---------------- 2. zero A@x scratch ----------------
__global__ void zero_ax_kernel() {
    size_t i = (size_t)blockIdx.x * blockDim.x + threadIdx.x;
    if (i < (size_t)N_NODES * XP / 4)
        ((float4*)g_ax)[i] = make_float4(0.f, 0.f, 0.f, 0.f);
}

// ---------------- 3. SpMM1: ax[row] += val * x[col], warp per edge ---------
__global__ void spmm_x_kernel(const float* __restrict__ val,
                              const int* __restrict__ row,
                              const int* __restrict__ col) {
    int e = (blockIdx.x * blockDim.x + threadIdx.x) >> 5;
    int lane = threadIdx.x & 31;
    if (e >= N_EDGES) return;
    int r = row[e], c = col[e];
    float v = val[e];
    const float* src = g_x + (size_t)c * XP;
    float* dst = g_ax + (size_t)r * XP;
    atomicAdd(dst + lane, v * src[lane]);
    atomicAdd(dst + lane + 32, v * src[lane + 32]);
    if (lane < D_IN - 64) atomicAdd(dst + lane + 64, v * src[lane + 64]);
}

// ---------------- 4. GEMM1: h = relu(ax @ W1 + b1) --------------------------
// BM=128, BN=128, K=83 whole. 256 thr, micro-tile 8x8 with fma.rn.f32x2.
#define AS_STRIDE 97
#define WS_STRIDE 132
#define GEMM1_SMEM ((128 * AS_STRIDE + 83 * WS_STRIDE) * 4)

__global__ __launch_bounds__(256) void gemm1_kernel(const float* __restrict__ W1,
                                                    const float* __restrict__ b1) {
    extern __shared__ float sm[];
    float* As = sm;                        // [128][97]
    float* Ws = sm + 128 * AS_STRIDE;      // [83][132]
    int t = threadIdx.x;
    int m0 = blockIdx.x * 128;
    int n0 = blockIdx.y * 128;

    // load A tile: rows m0..m0+127, 24 float4 each
    #pragma unroll
    for (int it = 0; it < 12; it++) {
        int flat = it * 256 + t;           // 0..3071
        int rr = flat / 24, q = flat % 24;
        float4 v = make_float4(0.f, 0.f, 0.f, 0.f);
        int gr = m0 + rr;
        if (gr < N_NODES) v = *(const float4*)&g_ax[(size_t)gr * XP + q * 4];
        float* dst = &As[rr * AS_STRIDE + q * 4];
        dst[0] = v.x; dst[1] = v.y; dst[2] = v.z; dst[3] = v.w;
    }
    // load W1 tile [83][128]
    for (int flat = t; flat < 83 * 32; flat += 256) {
        int k = flat / 32, j4 = flat % 32;
        float4 v = *(const float4*)&W1[(size_t)k * D_HID + n0 + j4 * 4];
        *(float4*)&Ws[k * WS_STRIDE + j4 * 4] = v;
    }
    __syncthreads();

    int warp = t >> 5, lane = t & 31;
    int wrow = (warp & 3) * 32;
    int wcol = (warp >> 2) * 64;
    int lr = lane >> 3;   // 0..3
    int lc = lane & 7;    // 0..7
    int rbase = wrow + lr * 8;
    int cbase = wcol + lc * 8;

    ull acc[4][8];
    #pragma unroll
    for (int i = 0; i < 4; i++)
        #pragma unroll
        for (int j = 0; j < 8; j++) acc[i][j] = 0ull;

    const float* ap = &As[rbase * AS_STRIDE];
    for (int k = 0; k < D_IN; k++) {
        float a[8];
        #pragma unroll
        for (int i = 0; i < 8; i++) a[i] = ap[i * AS_STRIDE + k];
        ull a2[4];
        #pragma unroll
        for (int i = 0; i < 4; i++) a2[i] = pack2(a[2 * i], a[2 * i + 1]);
        float4 bv0 = *(float4*)&Ws[k * WS_STRIDE + cbase];
        float4 bv1 = *(float4*)&Ws[k * WS_STRIDE + cbase + 4];
        ull bd[8];
        bd[0] = dup2(bv0.x); bd[1] = dup2(bv0.y); bd[2] = dup2(bv0.z); bd[3] = dup2(bv0.w);
        bd[4] = dup2(bv1.x); bd[5] = dup2(bv1.y); bd[6] = dup2(bv1.z); bd[7] = dup2(bv1.w);
        #pragma unroll
        for (int i = 0; i < 4; i++)
            #pragma unroll
            for (int j = 0; j < 8; j++)
                fma2(acc[i][j], a2[i], bd[j]);
    }

    float bias[8];
    #pragma unroll
    for (int j = 0; j < 8; j++) bias[j] = b1[n0 + cbase + j];

    #pragma unroll
    for (int i2 = 0; i2 < 4; i2++) {
        float lo[8], hi[8];
        #pragma unroll
        for (int j = 0; j < 8; j++) unpack2(acc[i2][j], lo[j], hi[j]);
        int r0 = m0 + rbase + 2 * i2;
        if (r0 < N_NODES) {
            float4 o0 = make_float4(fmaxf(lo[0] + bias[0], 0.f), fmaxf(lo[1] + bias[1], 0.f),
                                    fmaxf(lo[2] + bias[2], 0.f), fmaxf(lo[3] + bias[3], 0.f));
            float4 o1 = make_float4(fmaxf(lo[4] + bias[4], 0.f), fmaxf(lo[5] + bias[5], 0.f),
                                    fmaxf(lo[6] + bias[6], 0.f), fmaxf(lo[7] + bias[7], 0.f));
            *(float4*)&g_h[(size_t)r0 * D_HID + n0 + cbase] = o0;
            *(float4*)&g_h[(size_t)r0 * D_HID + n0 + cbase + 4] = o1;
        }
        if (r0 + 1 < N_NODES) {
            float4 o0 = make_float4(fmaxf(hi[0] + bias[0], 0.f), fmaxf(hi[1] + bias[1], 0.f),
                                    fmaxf(hi[2] + bias[2], 0.f), fmaxf(hi[3] + bias[3], 0.f));
            float4 o1 = make_float4(fmaxf(hi[4] + bias[4], 0.f), fmaxf(hi[5] + bias[5], 0.f),
                                    fmaxf(hi[6] + bias[6], 0.f), fmaxf(hi[7] + bias[7], 0.f));
            *(float4*)&g_h[(size_t)(r0 + 1) * D_HID + n0 + cbase] = o0;
            *(float4*)&g_h[(size_t)(r0 + 1) * D_HID + n0 + cbase + 4] = o1;
        }
    }
}

// ---------------- 5. GEMM2: z = h @ W2 (no bias), warp per 4 rows ----------
#define GEMM2_SMEM (D_HID * NC * 4)
#define N_QUADS (N_NODES / 4)

__global__ __launch_bounds__(256) void gemm2_kernel(const float* __restrict__ W2) {
    extern __shared__ float sW[];  // [1024*25]
    int t = threadIdx.x;
    for (int i = t; i < D_HID * NC; i += 256) sW[i] = W2[i];
    __syncthreads();

    int lane = t & 31;
    int gwarp = (blockIdx.x * 256 + t) >> 5;
    int nwarps = gridDim.x * 8;

    for (int q = gwarp; q < N_QUADS; q += nwarps) {
        int r0 = q * 4;
        const float* h0 = g_h + (size_t)r0 * D_HID;
        ull acc0[NC], acc1[NC];
        #pragma unroll
        for (int c = 0; c < NC; c++) { acc0[c] = 0ull; acc1[c] = 0ull; }

        for (int i = 0; i < 32; i++) {
            int k = i * 32 + lane;
            float x0 = h0[k];
            float x1 = h0[D_HID + k];
            float x2 = h0[2 * D_HID + k];
            float x3 = h0[3 * D_HID + k];
            ull p01 = pack2(x0, x1), p23 = pack2(x2, x3);
            const float* w = &sW[k * NC];
            #pragma unroll
            for (int c = 0; c < NC; c++) {
                ull wd = dup2(w[c]);
                fma2(acc0[c], p01, wd);
                fma2(acc1[c], p23, wd);
            }
        }
        // warp butterfly reduce (packed f32x2 adds)
        #pragma unroll
        for (int c = 0; c < NC; c++) {
            #pragma unroll
            for (int off = 16; off > 0; off >>= 1) {
                acc0[c] = add2(acc0[c], __shfl_xor_sync(0xffffffffu, acc0[c], off));
                acc1[c] = add2(acc1[c], __shfl_xor_sync(0xffffffffu, acc1[c], off));
            }
        }
        float o0 = 0.f, o1 = 0.f, o2 = 0.f, o3 = 0.f;
        #pragma unroll
        for (int c = 0; c < NC; c++) {
            if (lane == c) {
                unpack2(acc0[c], o0, o1);
                unpack2(acc1[c], o2, o3);
            }
        }
        if (lane < NC) {
            g_z[(size_t)(r0 + 0) * ZP + lane] = o0;
            g_z[(size_t)(r0 + 1) * ZP + lane] = o1;
            g_z[(size_t)(r0 + 2) * ZP + lane] = o2;
            g_z[(size_t)(r0 + 3) * ZP + lane] = o3;
        }
    }
}

// ---------------- 6. init output with b2 ----------------
__global__ void init_out_kernel(float* __restrict__ out, const float* __restrict__ b2) {
    int idx = blockIdx.x * blockDim.x + threadIdx.x;
    if (idx < N_NODES * NC) out[idx] = b2[idx % NC];
}

// ---------------- 7. SpMM2: out[row] += val * z[col], warp per edge --------
__global__ void spmm_z_kernel(const float* __restrict__ val,
                              const int* __restrict__ row,
                              const int* __restrict__ col,
                              float* __restrict__ out) {
    int e = (blockIdx.x * blockDim.x + threadIdx.x) >> 5;
    int lane = threadIdx.x & 31;
    if (e >= N_EDGES) return;
    if (lane < NC) {
        int r = row[e], c = col[e];
        float v = val[e];
        float zv = g_z[(size_t)c * ZP + lane];
        atomicAdd(out + (size_t)r * NC + lane, v * zv);
    }
}

// ---------------- launch ----------------
extern "C" void kernel_launch(void* const* d_in, const int* in_sizes, int n_in,
                              void* d_out, int out_size) {
    const float* feature = (const float*)d_in[0];
    const float* conv_w  = (const float*)d_in[1];
    const float* conv_b  = (const float*)d_in[2];
    const float* W1      = (const float*)d_in[3];
    const float* b1      = (const float*)d_in[4];
    const float* W2      = (const float*)d_in[5];
    const float* b2      = (const float*)d_in[6];
    const float* adj_val = (const float*)d_in[7];
    const int*   e_row   = (const int*)d_in[8];
    const int*   e_col   = (const int*)d_in[9];
    float* out = (float*)d_out;

    cudaFuncSetAttribute(gemm1_kernel, cudaFuncAttributeMaxDynamicSharedMemorySize, GEMM1_SMEM);
    cudaFuncSetAttribute(gemm2_kernel, cudaFuncAttributeMaxDynamicSharedMemorySize, GEMM2_SMEM);

    // 1. conv prelude
    conv_relu_kernel<<<N_NODES, 96>>>(feature, conv_w, conv_b);
    // 2. zero ax
    zero_ax_kernel<<<(N_NODES * XP / 4 + 255) / 256, 256>>>();
    // 3. SpMM on x (83-wide rows) — the cheap side of the reassociation
    spmm_x_kernel<<<N_EDGES / 8, 256>>>(adj_val, e_row, e_col);
    // 4. h = relu(ax @ W1 + b1)
    {
        dim3 grid((N_NODES + 127) / 128, D_HID / 128);
        gemm1_kernel<<<grid, 256, GEMM1_SMEM>>>(W1, b1);
    }
    // 5. z = h @ W2
    gemm2_kernel<<<296, 256, GEMM2_SMEM>>>(W2);
    // 6. out = b2 (broadcast)
    init_out_kernel<<<(N_NODES * NC + 255) / 256, 256>>>(out, b2);
    // 7. out += A @ z
    spmm_z_kernel<<<N_EDGES / 8, 256>>>(adj_val, e_row, e_col, out);
}

// round 3
// speedup vs baseline: 1.4660x; 1.4660x over previous
#include <cuda_runtime.h>

#define N_NODES 100000
#define N_EDGES 3200000
#define D_IN 83
#define XP 96          // padded x row stride (384B = 3 x 128B lines)
#define D_HID 1024
#define NC 25
#define ZP 32          // padded z row stride (128B = 1 line)
#define NBLK 391       // ceil(N_NODES/256) for scan

// ---------------- scratch (device globals; no allocation allowed) ----------
__device__ float g_x[(size_t)N_NODES * XP];    // conv output, padded (pad cols = 0)
__device__ float g_ax[(size_t)N_NODES * XP];   // A @ x
__device__ float g_h[(size_t)N_NODES * D_HID]; // hidden layer (409.6 MB)
__device__ float g_z[(size_t)N_NODES * ZP];    // h @ W2, padded
// CSR build
__device__ int   g_cnt[N_NODES];
__device__ int   g_rowptr[N_NODES + 1];
__device__ int   g_cur[N_NODES + 1];
__device__ int   g_bsum[NBLK];
__device__ int   g_boff[NBLK];
__device__ int   g_ecol[N_EDGES];
__device__ float g_eval[N_EDGES];

typedef unsigned long long ull;

__device__ __forceinline__ ull dup2(float x) {
    ull r; asm("mov.b64 %0, {%1, %1};" : "=l"(r) : "f"(x)); return r;
}
__device__ __forceinline__ ull pack2(float lo, float hi) {
    ull r; asm("mov.b64 %0, {%1, %2};" : "=l"(r) : "f"(lo), "f"(hi)); return r;
}
__device__ __forceinline__ void unpack2(ull v, float& lo, float& hi) {
    asm("mov.b64 {%0, %1}, %2;" : "=f"(lo), "=f"(hi) : "l"(v));
}
__device__ __forceinline__ void fma2(ull& d, ull a, ull b) {
    asm("fma.rn.f32x2 %0, %1, %2, %0;" : "+l"(d) : "l"(a), "l"(b));
}
__device__ __forceinline__ ull add2(ull a, ull b) {
    ull r; asm("add.rn.f32x2 %0, %1, %2;" : "=l"(r) : "l"(a), "l"(b)); return r;
}

// ---------------- 1. conv1d(1->4,k5,p2) + channel-sum + relu ----------------
__global__ void conv_relu_kernel(const float* __restrict__ feat,
                                 const float* __restrict__ conv_w,
                                 const float* __restrict__ conv_b) {
    __shared__ float srow[D_IN];
    __shared__ float sw[5];
    __shared__ float sb;
    int n = blockIdx.x;
    int t = threadIdx.x;  // 96 threads
    if (t < 5) sw[t] = conv_w[t] + conv_w[5 + t] + conv_w[10 + t] + conv_w[15 + t];
    if (t == 5) sb = conv_b[0] + conv_b[1] + conv_b[2] + conv_b[3];
    if (t < D_IN) srow[t] = feat[(size_t)n * D_IN + t];
    __syncthreads();
    float r = 0.f;
    if (t < D_IN) {
        float s = sb;
        #pragma unroll
        for (int k = 0; k < 5; k++) {
            int j = t + k - 2;
            if (j >= 0 && j < D_IN) s += srow[j] * sw[k];
        }
        r = fmaxf(s, 0.f);
    }
    g_x[(size_t)n * XP + t] = r;  // cols 83..95 get 0
}

// ---------------- CSR build: count -> scan -> scatter ----------------------
__global__ void zero_cnt_kernel() {
    int i = blockIdx.x * blockDim.x + threadIdx.x;
    if (i < N_NODES) g_cnt[i] = 0;
}

__global__ void count_kernel(const int* __restrict__ row) {
    int e = blockIdx.x * blockDim.x + threadIdx.x;
    if (e < N_EDGES) atomicAdd(&g_cnt[row[e]], 1);
}

__global__ void scan1_kernel() {
    __shared__ int s[256];
    int t = threadIdx.x;
    int i = blockIdx.x * 256 + t;
    int v = (i < N_NODES) ? g_cnt[i] : 0;
    s[t] = v;
    __syncthreads();
    #pragma unroll
    for (int d = 1; d < 256; d <<= 1) {
        int x = (t >= d) ? s[t - d] : 0;
        __syncthreads();
        s[t] += x;
        __syncthreads();
    }
    if (i < N_NODES) g_rowptr[i + 1] = s[t];
    if (t == 255) g_bsum[blockIdx.x] = s[255];
}

__global__ void scan2_kernel() {
    __shared__ int s[512];
    int t = threadIdx.x;
    s[t] = (t < NBLK) ? g_bsum[t] : 0;
    __syncthreads();
    #pragma unroll
    for (int d = 1; d < 512; d <<= 1) {
        int x = (t >= d) ? s[t - d] : 0;
        __syncthreads();
        s[t] += x;
        __syncthreads();
    }
    if (t < NBLK) g_boff[t] = (t > 0) ? s[t - 1] : 0;
}

__global__ void scan3_kernel() {
    int t = threadIdx.x;
    int i = blockIdx.x * 256 + t;
    if (i < N_NODES) {
        int val = g_rowptr[i + 1] + g_boff[blockIdx.x];
        g_rowptr[i + 1] = val;
        g_cur[i + 1] = val;
    }
    if (i == 0) { g_rowptr[0] = 0; g_cur[0] = 0; }
}

__global__ void scatter_kernel(const float* __restrict__ val,
                               const int* __restrict__ row,
                               const int* __restrict__ col) {
    int e = blockIdx.x * blockDim.x + threadIdx.x;
    if (e < N_EDGES) {
        int r = row[e];
        int pos = atomicAdd(&g_cur[r], 1);
        g_ecol[pos] = col[e];
        g_eval[pos] = val[e];
    }
}

// ---------------- 3. SpMM1 (gather): ax[r] = sum_j val_j * x[col_j] --------
__global__ void spmm_x_csr_kernel() {
    int w = (blockIdx.x * blockDim.x + threadIdx.x) >> 5;
    int lane = threadIdx.x & 31;
    if (w >= N_NODES) return;
    int s = g_rowptr[w], e = g_rowptr[w + 1];
    float a0 = 0.f, a1 = 0.f, a2 = 0.f;
    float b0 = 0.f, b1 = 0.f, b2 = 0.f;
    int j = s;
    for (; j + 1 < e; j += 2) {
        int   c0 = g_ecol[j],   c1 = g_ecol[j + 1];
        float v0 = g_eval[j],   v1 = g_eval[j + 1];
        const float* s0 = g_x + (size_t)c0 * XP;
        const float* s1 = g_x + (size_t)c1 * XP;
        a0 = fmaf(v0, s0[lane],      a0);
        a1 = fmaf(v0, s0[lane + 32], a1);
        a2 = fmaf(v0, s0[lane + 64], a2);
        b0 = fmaf(v1, s1[lane],      b0);
        b1 = fmaf(v1, s1[lane + 32], b1);
        b2 = fmaf(v1, s1[lane + 64], b2);
    }
    if (j < e) {
        int c0 = g_ecol[j]; float v0 = g_eval[j];
        const float* s0 = g_x + (size_t)c0 * XP;
        a0 = fmaf(v0, s0[lane],      a0);
        a1 = fmaf(v0, s0[lane + 32], a1);
        a2 = fmaf(v0, s0[lane + 64], a2);
    }
    float* dst = g_ax + (size_t)w * XP;
    dst[lane]      = a0 + b0;
    dst[lane + 32] = a1 + b1;
    dst[lane + 64] = a2 + b2;   // cols 83..95 are sums of x-pad zeros -> 0
}

// ---------------- 4. GEMM1: h = relu(ax @ W1 + b1) --------------------------
// BM=128, BN=128, K=83. A tile stored k-major (transposed) so row pairs load
// as single LDS.64 -> ready-packed f32x2 operands.
#define RT 130                         // As_t row stride (even: keeps 8B align)
#define WS_STRIDE 132
#define GEMM1_SMEM ((96 * RT + 83 * WS_STRIDE) * 4)

__global__ __launch_bounds__(256) void gemm1_kernel(const float* __restrict__ W1,
                                                    const float* __restrict__ b1) {
    extern __shared__ float sm[];
    float* As_t = sm;                        // [96][130]  (k-major)
    float* Ws = sm + 96 * RT;                // [83][132]
    int t = threadIdx.x;
    int m0 = blockIdx.x * 128;
    int n0 = blockIdx.y * 128;

    // load A tile transposed: rows m0..m0+127, 24 float4 each -> As_t[k][row]
    #pragma unroll
    for (int it = 0; it < 12; it++) {
        int flat = it * 256 + t;           // 0..3071
        int rr = flat / 24, q = flat % 24;
        float4 v = make_float4(0.f, 0.f, 0.f, 0.f);
        int gr = m0 + rr;
        if (gr < N_NODES) v = *(const float4*)&g_ax[(size_t)gr * XP + q * 4];
        int k0 = q * 4;
        As_t[(k0 + 0) * RT + rr] = v.x;
        As_t[(k0 + 1) * RT + rr] = v.y;
        As_t[(k0 + 2) * RT + rr] = v.z;
        As_t[(k0 + 3) * RT + rr] = v.w;
    }
    // load W1 tile [83][128]
    for (int flat = t; flat < 83 * 32; flat += 256) {
        int k = flat / 32, j4 = flat % 32;
        float4 v = *(const float4*)&W1[(size_t)k * D_HID + n0 + j4 * 4];
        *(float4*)&Ws[k * WS_STRIDE + j4 * 4] = v;
    }
    __syncthreads();

    int warp = t >> 5, lane = t & 31;
    int wrow = (warp & 3) * 32;
    int wcol = (warp >> 2) * 64;
    int lr = lane >> 3;   // 0..3
    int lc = lane & 7;    // 0..7
    int rbase = wrow + lr * 8;
    int cbase = wcol + lc * 8;

    ull acc[4][8];
    #pragma unroll
    for (int i = 0; i < 4; i++)
        #pragma unroll
        for (int j = 0; j < 8; j++) acc[i][j] = 0ull;

    for (int k = 0; k < D_IN; k++) {
        const float* arow = &As_t[k * RT + rbase];
        ull a2[4];
        #pragma unroll
        for (int i = 0; i < 4; i++)
            a2[i] = *(const ull*)&arow[2 * i];   // LDS.64: rows (rbase+2i, +2i+1)
        float4 bv0 = *(float4*)&Ws[k * WS_STRIDE + cbase];
        float4 bv1 = *(float4*)&Ws[k * WS_STRIDE + cbase + 4];
        ull bd[8];
        bd[0] = dup2(bv0.x); bd[1] = dup2(bv0.y); bd[2] = dup2(bv0.z); bd[3] = dup2(bv0.w);
        bd[4] = dup2(bv1.x); bd[5] = dup2(bv1.y); bd[6] = dup2(bv1.z); bd[7] = dup2(bv1.w);
        #pragma unroll
        for (int i = 0; i < 4; i++)
            #pragma unroll
            for (int j = 0; j < 8; j++)
                fma2(acc[i][j], a2[i], bd[j]);
    }

    float bias[8];
    #pragma unroll
    for (int j = 0; j < 8; j++) bias[j] = b1[n0 + cbase + j];

    #pragma unroll
    for (int i2 = 0; i2 < 4; i2++) {
        float lo[8], hi[8];
        #pragma unroll
        for (int j = 0; j < 8; j++) unpack2(acc[i2][j], lo[j], hi[j]);
        int r0 = m0 + rbase + 2 * i2;
        if (r0 < N_NODES) {
            float4 o0 = make_float4(fmaxf(lo[0] + bias[0], 0.f), fmaxf(lo[1] + bias[1], 0.f),
                                    fmaxf(lo[2] + bias[2], 0.f), fmaxf(lo[3] + bias[3], 0.f));
            float4 o1 = make_float4(fmaxf(lo[4] + bias[4], 0.f), fmaxf(lo[5] + bias[5], 0.f),
                                    fmaxf(lo[6] + bias[6], 0.f), fmaxf(lo[7] + bias[7], 0.f));
            *(float4*)&g_h[(size_t)r0 * D_HID + n0 + cbase] = o0;
            *(float4*)&g_h[(size_t)r0 * D_HID + n0 + cbase + 4] = o1;
        }
        if (r0 + 1 < N_NODES) {
            float4 o0 = make_float4(fmaxf(hi[0] + bias[0], 0.f), fmaxf(hi[1] + bias[1], 0.f),
                                    fmaxf(hi[2] + bias[2], 0.f), fmaxf(hi[3] + bias[3], 0.f));
            float4 o1 = make_float4(fmaxf(hi[4] + bias[4], 0.f), fmaxf(hi[5] + bias[5], 0.f),
                                    fmaxf(hi[6] + bias[6], 0.f), fmaxf(hi[7] + bias[7], 0.f));
            *(float4*)&g_h[(size_t)(r0 + 1) * D_HID + n0 + cbase] = o0;
            *(float4*)&g_h[(size_t)(r0 + 1) * D_HID + n0 + cbase + 4] = o1;
        }
    }
}

// ---------------- 5. GEMM2: z = h @ W2 (no bias), warp per 4 rows ----------
#define GEMM2_SMEM (D_HID * NC * 4)
#define N_QUADS (N_NODES / 4)

__global__ __launch_bounds__(256) void gemm2_kernel(const float* __restrict__ W2) {
    extern __shared__ float sW[];  // [1024*25]
    int t = threadIdx.x;
    for (int i = t; i < D_HID * NC; i += 256) sW[i] = W2[i];
    __syncthreads();

    int lane = t & 31;
    int gwarp = (blockIdx.x * 256 + t) >> 5;
    int nwarps = gridDim.x * 8;

    for (int q = gwarp; q < N_QUADS; q += nwarps) {
        int r0 = q * 4;
        const float* h0 = g_h + (size_t)r0 * D_HID;
        ull acc0[NC], acc1[NC];
        #pragma unroll
        for (int c = 0; c < NC; c++) { acc0[c] = 0ull; acc1[c] = 0ull; }

        for (int i = 0; i < 32; i++) {
            int k = i * 32 + lane;
            float x0 = h0[k];
            float x1 = h0[D_HID + k];
            float x2 = h0[2 * D_HID + k];
            float x3 = h0[3 * D_HID + k];
            ull p01 = pack2(x0, x1), p23 = pack2(x2, x3);
            const float* w = &sW[k * NC];
            #pragma unroll
            for (int c = 0; c < NC; c++) {
                ull wd = dup2(w[c]);
                fma2(acc0[c], p01, wd);
                fma2(acc1[c], p23, wd);
            }
        }
        #pragma unroll
        for (int c = 0; c < NC; c++) {
            #pragma unroll
            for (int off = 16; off > 0; off >>= 1) {
                acc0[c] = add2(acc0[c], __shfl_xor_sync(0xffffffffu, acc0[c], off));
                acc1[c] = add2(acc1[c], __shfl_xor_sync(0xffffffffu, acc1[c], off));
            }
        }
        float o0 = 0.f, o1 = 0.f, o2 = 0.f, o3 = 0.f;
        #pragma unroll
        for (int c = 0; c < NC; c++) {
            if (lane == c) {
                unpack2(acc0[c], o0, o1);
                unpack2(acc1[c], o2, o3);
            }
        }
        if (lane < NC) {
            g_z[(size_t)(r0 + 0) * ZP + lane] = o0;
            g_z[(size_t)(r0 + 1) * ZP + lane] = o1;
            g_z[(size_t)(r0 + 2) * ZP + lane] = o2;
            g_z[(size_t)(r0 + 3) * ZP + lane] = o3;
        }
    }
}

// ---------------- 7. SpMM2 (gather): out[r] = b2 + sum val_j * z[col_j] ----
__global__ void spmm_z_csr_kernel(const float* __restrict__ b2,
                                  float* __restrict__ out) {
    int w = (blockIdx.x * blockDim.x + threadIdx.x) >> 5;
    int lane = threadIdx.x & 31;
    if (w >= N_NODES) return;
    int s = g_rowptr[w], e = g_rowptr[w + 1];
    float acc = 0.f, accb = 0.f;
    int j = s;
    for (; j + 1 < e; j += 2) {
        int   c0 = g_ecol[j],   c1 = g_ecol[j + 1];
        float v0 = g_eval[j],   v1 = g_eval[j + 1];
        acc  = fmaf(v0, g_z[(size_t)c0 * ZP + lane], acc);
        accb = fmaf(v1, g_z[(size_t)c1 * ZP + lane], accb);
    }
    if (j < e) {
        int c0 = g_ecol[j]; float v0 = g_eval[j];
        acc = fmaf(v0, g_z[(size_t)c0 * ZP + lane], acc);
    }
    if (lane < NC)
        out[(size_t)w * NC + lane] = acc + accb + b2[lane];
}

// ---------------- launch ----------------
extern "C" void kernel_launch(void* const* d_in, const int* in_sizes, int n_in,
                              void* d_out, int out_size) {
    const float* feature = (const float*)d_in[0];
    const float* conv_w  = (const float*)d_in[1];
    const float* conv_b  = (const float*)d_in[2];
    const float* W1      = (const float*)d_in[3];
    const float* b1      = (const float*)d_in[4];
    const float* W2      = (const float*)d_in[5];
    const float* b2      = (const float*)d_in[6];
    const float* adj_val = (const float*)d_in[7];
    const int*   e_row   = (const int*)d_in[8];
    const int*   e_col   = (const int*)d_in[9];
    float* out = (float*)d_out;

    cudaFuncSetAttribute(gemm1_kernel, cudaFuncAttributeMaxDynamicSharedMemorySize, GEMM1_SMEM);
    cudaFuncSetAttribute(gemm2_kernel, cudaFuncAttributeMaxDynamicSharedMemorySize, GEMM2_SMEM);

    const int EB = (N_EDGES + 255) / 256;       // 12500
    const int WB = (N_NODES * 32 + 255) / 256;  // 12500 (warp per row)

    // 1. conv prelude
    conv_relu_kernel<<<N_NODES, 96>>>(feature, conv_w, conv_b);
    // 2. CSR build
    zero_cnt_kernel<<<NBLK, 256>>>();
    count_kernel<<<EB, 256>>>(e_row);
    scan1_kernel<<<NBLK, 256>>>();
    scan2_kernel<<<1, 512>>>();
    scan3_kernel<<<NBLK, 256>>>();
    scatter_kernel<<<EB, 256>>>(adj_val, e_row, e_col);
    // 3. ax = A @ x (gather)
    spmm_x_csr_kernel<<<WB, 256>>>();
    // 4. h = relu(ax @ W1 + b1)
    {
        dim3 grid((N_NODES + 127) / 128, D_HID / 128);
        gemm1_kernel<<<grid, 256, GEMM1_SMEM>>>(W1, b1);
    }
    // 5. z = h @ W2
    gemm2_kernel<<<296, 256, GEMM2_SMEM>>>(W2);
    // 6+7. out = A @ z + b2 (gather, bias fused)
    spmm_z_csr_kernel<<<WB, 256>>>(b2, out);
}

// round 5
// speedup vs baseline: 1.7530x; 1.1958x over previous
#include <cuda_runtime.h>
#include <cstdint>

#define N_NODES 100000
#define N_EDGES 3200000
#define D_IN 83
#define XP 96          // padded x row stride
#define D_HID 1024
#define NC 25
#define ZP 32
#define NBLK 391

// ---------------- scratch ----------------
__device__ float g_x[(size_t)N_NODES * XP];
__device__ float g_ax[(size_t)N_NODES * XP];
__device__ float g_h[(size_t)N_NODES * D_HID];
__device__ float g_z[(size_t)N_NODES * ZP];
__device__ int   g_cnt[N_NODES];
__device__ int   g_rowptr[N_NODES + 1];
__device__ int   g_cur[N_NODES + 1];
__device__ int   g_bsum[NBLK];
__device__ int   g_boff[NBLK];
__device__ int   g_ecol[N_EDGES];
__device__ float g_eval[N_EDGES];

typedef unsigned long long ull;

__device__ __forceinline__ ull dup2(float x) {
    ull r; asm("mov.b64 %0, {%1, %1};" : "=l"(r) : "f"(x)); return r;
}
__device__ __forceinline__ ull pack2(float lo, float hi) {
    ull r; asm("mov.b64 %0, {%1, %2};" : "=l"(r) : "f"(lo), "f"(hi)); return r;
}
__device__ __forceinline__ void unpack2(ull v, float& lo, float& hi) {
    asm("mov.b64 {%0, %1}, %2;" : "=f"(lo), "=f"(hi) : "l"(v));
}
__device__ __forceinline__ void fma2(ull& d, ull a, ull b) {
    asm("fma.rn.f32x2 %0, %1, %2, %0;" : "+l"(d) : "l"(a), "l"(b));
}
__device__ __forceinline__ ull add2(ull a, ull b) {
    ull r; asm("add.rn.f32x2 %0, %1, %2;" : "=l"(r) : "l"(a), "l"(b)); return r;
}
__device__ __forceinline__ float to_tf32(float v) {
    float r;
    asm("cvt.rna.tf32.f32 %0, %1;" : "=f"(r) : "f"(v));
    return r;
}

// ---------------- 1. conv prelude ----------------
__global__ void conv_relu_kernel(const float* __restrict__ feat,
                                 const float* __restrict__ conv_w,
                                 const float* __restrict__ conv_b) {
    __shared__ float srow[D_IN];
    __shared__ float sw[5];
    __shared__ float sb;
    int n = blockIdx.x;
    int t = threadIdx.x;
    if (t < 5) sw[t] = conv_w[t] + conv_w[5 + t] + conv_w[10 + t] + conv_w[15 + t];
    if (t == 5) sb = conv_b[0] + conv_b[1] + conv_b[2] + conv_b[3];
    if (t < D_IN) srow[t] = feat[(size_t)n * D_IN + t];
    __syncthreads();
    float r = 0.f;
    if (t < D_IN) {
        float s = sb;
        #pragma unroll
        for (int k = 0; k < 5; k++) {
            int j = t + k - 2;
            if (j >= 0 && j < D_IN) s += srow[j] * sw[k];
        }
        r = fmaxf(s, 0.f);
    }
    g_x[(size_t)n * XP + t] = r;
}

// ---------------- CSR build ----------------
__global__ void zero_cnt_kernel() {
    int i = blockIdx.x * blockDim.x + threadIdx.x;
    if (i < N_NODES) g_cnt[i] = 0;
}
__global__ void count_kernel(const int* __restrict__ row) {
    int e = blockIdx.x * blockDim.x + threadIdx.x;
    if (e < N_EDGES) atomicAdd(&g_cnt[row[e]], 1);
}
__global__ void scan1_kernel() {
    __shared__ int s[256];
    int t = threadIdx.x;
    int i = blockIdx.x * 256 + t;
    int v = (i < N_NODES) ? g_cnt[i] : 0;
    s[t] = v;
    __syncthreads();
    #pragma unroll
    for (int d = 1; d < 256; d <<= 1) {
        int x = (t >= d) ? s[t - d] : 0;
        __syncthreads();
        s[t] += x;
        __syncthreads();
    }
    if (i < N_NODES) g_rowptr[i + 1] = s[t];
    if (t == 255) g_bsum[blockIdx.x] = s[255];
}
__global__ void scan2_kernel() {
    __shared__ int s[512];
    int t = threadIdx.x;
    s[t] = (t < NBLK) ? g_bsum[t] : 0;
    __syncthreads();
    #pragma unroll
    for (int d = 1; d < 512; d <<= 1) {
        int x = (t >= d) ? s[t - d] : 0;
        __syncthreads();
        s[t] += x;
        __syncthreads();
    }
    if (t < NBLK) g_boff[t] = (t > 0) ? s[t - 1] : 0;
}
__global__ void scan3_kernel() {
    int t = threadIdx.x;
    int i = blockIdx.x * 256 + t;
    if (i < N_NODES) {
        int val = g_rowptr[i + 1] + g_boff[blockIdx.x];
        g_rowptr[i + 1] = val;
        g_cur[i + 1] = val;
    }
    if (i == 0) { g_rowptr[0] = 0; g_cur[0] = 0; }
}
__global__ void scatter_kernel(const float* __restrict__ val,
                               const int* __restrict__ row,
                               const int* __restrict__ col) {
    int e = blockIdx.x * blockDim.x + threadIdx.x;
    if (e < N_EDGES) {
        int r = row[e];
        int pos = atomicAdd(&g_cur[r], 1);
        g_ecol[pos] = col[e];
        g_eval[pos] = val[e];
    }
}

// ---------------- 3. SpMM1 (gather) ----------------
__global__ void spmm_x_csr_kernel() {
    int w = (blockIdx.x * blockDim.x + threadIdx.x) >> 5;
    int lane = threadIdx.x & 31;
    if (w >= N_NODES) return;
    int s = g_rowptr[w], e = g_rowptr[w + 1];
    float a0 = 0.f, a1 = 0.f, a2 = 0.f;
    float b0 = 0.f, b1 = 0.f, b2 = 0.f;
    int j = s;
    for (; j + 1 < e; j += 2) {
        int   c0 = g_ecol[j],   c1 = g_ecol[j + 1];
        float v0 = g_eval[j],   v1 = g_eval[j + 1];
        const float* s0 = g_x + (size_t)c0 * XP;
        const float* s1 = g_x + (size_t)c1 * XP;
        a0 = fmaf(v0, s0[lane],      a0);
        a1 = fmaf(v0, s0[lane + 32], a1);
        a2 = fmaf(v0, s0[lane + 64], a2);
        b0 = fmaf(v1, s1[lane],      b0);
        b1 = fmaf(v1, s1[lane + 32], b1);
        b2 = fmaf(v1, s1[lane + 64], b2);
    }
    if (j < e) {
        int c0 = g_ecol[j]; float v0 = g_eval[j];
        const float* s0 = g_x + (size_t)c0 * XP;
        a0 = fmaf(v0, s0[lane],      a0);
        a1 = fmaf(v0, s0[lane + 32], a1);
        a2 = fmaf(v0, s0[lane + 64], a2);
    }
    float* dst = g_ax + (size_t)w * XP;
    dst[lane]      = a0 + b0;
    dst[lane + 32] = a1 + b1;
    dst[lane + 64] = a2 + b2;
}

// ---------------- 4. GEMM1 via mma.sync tf32: h = relu(ax @ W1 + b1) -------
// CTA tile 128x128, K=96 (12 k-steps of 8). 8 warps in 2x4; warp tile 64x32
// = 4x4 grid of m16n8k8. A smem [128][100], B smem [96][136] (conflict-free).
#define AST 100
#define BST 136
#define GT1_SMEM ((128 * AST + 96 * BST) * 4)

__device__ __forceinline__ void mma_tf32_16x8x8(float* d, const uint32_t* a, const uint32_t* b) {
    asm volatile(
        "mma.sync.aligned.m16n8k8.row.col.f32.tf32.tf32.f32 "
        "{%0,%1,%2,%3}, {%4,%5,%6,%7}, {%8,%9}, {%0,%1,%2,%3};"
        : "+f"(d[0]), "+f"(d[1]), "+f"(d[2]), "+f"(d[3])
        : "r"(a[0]), "r"(a[1]), "r"(a[2]), "r"(a[3]), "r"(b[0]), "r"(b[1]));
}

__global__ __launch_bounds__(256) void gemm1_mma_kernel(const float* __restrict__ W1,
                                                        const float* __restrict__ b1) {
    extern __shared__ float sm[];
    float* As = sm;                 // [128][100]
    float* Bs = sm + 128 * AST;     // [96][136]  Bs[k][n]
    int t = threadIdx.x;
    int wid = t >> 5, lane = t & 31;
    int m0 = blockIdx.x * 128;
    int n0 = blockIdx.y * 128;

    // stage A (tf32-rounded, zero-padded rows/cols)
    #pragma unroll
    for (int it = 0; it < 12; it++) {
        int flat = it * 256 + t;
        int rr = flat / 24, q = flat % 24;
        float4 v = make_float4(0.f, 0.f, 0.f, 0.f);
        int gr = m0 + rr;
        if (gr < N_NODES) v = *(const float4*)&g_ax[(size_t)gr * XP + q * 4];
        v.x = to_tf32(v.x); v.y = to_tf32(v.y); v.z = to_tf32(v.z); v.w = to_tf32(v.w);
        *(float4*)&As[rr * AST + q * 4] = v;
    }
    // stage B: Bs[k][n] = W1[k][n0+n] (k<83, else 0), coalesced float4
    #pragma unroll
    for (int it = 0; it < 12; it++) {
        int flat = it * 256 + t;     // 0..3071 = 96 k-rows * 32 float4
        int k = flat >> 5, n4 = flat & 31;
        float4 v = make_float4(0.f, 0.f, 0.f, 0.f);
        if (k < D_IN) {
            v = *(const float4*)&W1[(size_t)k * D_HID + n0 + n4 * 4];
            v.x = to_tf32(v.x); v.y = to_tf32(v.y); v.z = to_tf32(v.z); v.w = to_tf32(v.w);
        }
        *(float4*)&Bs[k * BST + n4 * 4] = v;
    }
    __syncthreads();

    int wm = (wid & 1) * 64;        // warp row origin in tile
    int wn = (wid >> 1) * 32;       // warp col origin in tile
    int g = lane >> 2;              // 0..7
    int tg = lane & 3;              // 0..3

    float acc[4][4][4];
    #pragma unroll
    for (int mt = 0; mt < 4; mt++)
        #pragma unroll
        for (int nt = 0; nt < 4; nt++)
            #pragma unroll
            for (int i = 0; i < 4; i++) acc[mt][nt][i] = 0.f;

    #pragma unroll
    for (int ks = 0; ks < 12; ks++) {
        int k0 = ks * 8;
        uint32_t a[4][4];
        #pragma unroll
        for (int mt = 0; mt < 4; mt++) {
            const float* ap = &As[(wm + mt * 16 + g) * AST + k0 + tg];
            a[mt][0] = __float_as_uint(ap[0]);
            a[mt][1] = __float_as_uint(ap[8 * AST]);
            a[mt][2] = __float_as_uint(ap[4]);
            a[mt][3] = __float_as_uint(ap[8 * AST + 4]);
        }
        uint32_t b[4][2];
        #pragma unroll
        for (int nt = 0; nt < 4; nt++) {
            const float* bp = &Bs[(k0 + tg) * BST + wn + nt * 8 + g];
            b[nt][0] = __float_as_uint(bp[0]);
            b[nt][1] = __float_as_uint(bp[4 * BST]);
        }
        #pragma unroll
        for (int mt = 0; mt < 4; mt++)
            #pragma unroll
            for (int nt = 0; nt < 4; nt++)
                mma_tf32_16x8x8(acc[mt][nt], a[mt], b[nt]);
    }

    // epilogue: bias + relu, guarded stores (float2 per c-pair)
    #pragma unroll
    for (int nt = 0; nt < 4; nt++) {
        int col = n0 + wn + nt * 8 + tg * 2;
        float bz0 = b1[col], bz1 = b1[col + 1];
        #pragma unroll
        for (int mt = 0; mt < 4; mt++) {
            int r0 = m0 + wm + mt * 16 + g;
            if (r0 < N_NODES) {
                float2 o;
                o.x = fmaxf(acc[mt][nt][0] + bz0, 0.f);
                o.y = fmaxf(acc[mt][nt][1] + bz1, 0.f);
                *(float2*)&g_h[(size_t)r0 * D_HID + col] = o;
            }
            int r1 = r0 + 8;
            if (r1 < N_NODES) {
                float2 o;
                o.x = fmaxf(acc[mt][nt][2] + bz0, 0.f);
                o.y = fmaxf(acc[mt][nt][3] + bz1, 0.f);
                *(float2*)&g_h[(size_t)r1 * D_HID + col] = o;
            }
        }
    }
}

// ---------------- 5. GEMM2: z = h @ W2, warp per 4 rows ----------
#define GEMM2_SMEM (D_HID * NC * 4)
#define N_QUADS (N_NODES / 4)

__global__ __launch_bounds__(256) void gemm2_kernel(const float* __restrict__ W2) {
    extern __shared__ float smem2[];
    float* sW = smem2;
    int t = threadIdx.x;
    for (int i = t; i < D_HID * NC; i += 256) sW[i] = W2[i];
    __syncthreads();

    int lane = t & 31;
    int gwarp = (blockIdx.x * 256 + t) >> 5;
    int nwarps = gridDim.x * 8;

    for (int q = gwarp; q < N_QUADS; q += nwarps) {
        int r0 = q * 4;
        const float* h0 = g_h + (size_t)r0 * D_HID;
        ull acc0[NC], acc1[NC];
        #pragma unroll
        for (int c = 0; c < NC; c++) { acc0[c] = 0ull; acc1[c] = 0ull; }

        for (int i = 0; i < 32; i++) {
            int k = i * 32 + lane;
            float x0 = h0[k];
            float x1 = h0[D_HID + k];
            float x2 = h0[2 * D_HID + k];
            float x3 = h0[3 * D_HID + k];
            ull p01 = pack2(x0, x1), p23 = pack2(x2, x3);
            const float* w = &sW[k * NC];
            #pragma unroll
            for (int c = 0; c < NC; c++) {
                ull wd = dup2(w[c]);
                fma2(acc0[c], p01, wd);
                fma2(acc1[c], p23, wd);
            }
        }
        #pragma unroll
        for (int c = 0; c < NC; c++) {
            #pragma unroll
            for (int off = 16; off > 0; off >>= 1) {
                acc0[c] = add2(acc0[c], __shfl_xor_sync(0xffffffffu, acc0[c], off));
                acc1[c] = add2(acc1[c], __shfl_xor_sync(0xffffffffu, acc1[c], off));
            }
        }
        float o0 = 0.f, o1 = 0.f, o2 = 0.f, o3 = 0.f;
        #pragma unroll
        for (int c = 0; c < NC; c++) {
            if (lane == c) {
                unpack2(acc0[c], o0, o1);
                unpack2(acc1[c], o2, o3);
            }
        }
        if (lane < NC) {
            g_z[(size_t)(r0 + 0) * ZP + lane] = o0;
            g_z[(size_t)(r0 + 1) * ZP + lane] = o1;
            g_z[(size_t)(r0 + 2) * ZP + lane] = o2;
            g_z[(size_t)(r0 + 3) * ZP + lane] = o3;
        }
    }
}

// ---------------- 7. SpMM2 (gather) ----------------
__global__ void spmm_z_csr_kernel(const float* __restrict__ b2,
                                  float* __restrict__ out) {
    int w = (blockIdx.x * blockDim.x + threadIdx.x) >> 5;
    int lane = threadIdx.x & 31;
    if (w >= N_NODES) return;
    int s = g_rowptr[w], e = g_rowptr[w + 1];
    float acc = 0.f, accb = 0.f;
    int j = s;
    for (; j + 1 < e; j += 2) {
        int   c0 = g_ecol[j],   c1 = g_ecol[j + 1];
        float v0 = g_eval[j],   v1 = g_eval[j + 1];
        acc  = fmaf(v0, g_z[(size_t)c0 * ZP + lane], acc);
        accb = fmaf(v1, g_z[(size_t)c1 * ZP + lane], accb);
    }
    if (j < e) {
        int c0 = g_ecol[j]; float v0 = g_eval[j];
        acc = fmaf(v0, g_z[(size_t)c0 * ZP + lane], acc);
    }
    if (lane < NC)
        out[(size_t)w * NC + lane] = acc + accb + b2[lane];
}

// ---------------- launch ----------------
extern "C" void kernel_launch(void* const* d_in, const int* in_sizes, int n_in,
                              void* d_out, int out_size) {
    const float* feature = (const float*)d_in[0];
    const float* conv_w  = (const float*)d_in[1];
    const float* conv_b  = (const float*)d_in[2];
    const float* W1      = (const float*)d_in[3];
    const float* b1      = (const float*)d_in[4];
    const float* W2      = (const float*)d_in[5];
    const float* b2      = (const float*)d_in[6];
    const float* adj_val = (const float*)d_in[7];
    const int*   e_row   = (const int*)d_in[8];
    const int*   e_col   = (const int*)d_in[9];
    float* out = (float*)d_out;

    cudaFuncSetAttribute(gemm1_mma_kernel, cudaFuncAttributeMaxDynamicSharedMemorySize, GT1_SMEM);
    cudaFuncSetAttribute(gemm2_kernel, cudaFuncAttributeMaxDynamicSharedMemorySize, GEMM2_SMEM);

    const int EB = (N_EDGES + 255) / 256;
    const int WB = (N_NODES * 32 + 255) / 256;

    conv_relu_kernel<<<N_NODES, 96>>>(feature, conv_w, conv_b);
    zero_cnt_kernel<<<NBLK, 256>>>();
    count_kernel<<<EB, 256>>>(e_row);
    scan1_kernel<<<NBLK, 256>>>();
    scan2_kernel<<<1, 512>>>();
    scan3_kernel<<<NBLK, 256>>>();
    scatter_kernel<<<EB, 256>>>(adj_val, e_row, e_col);
    spmm_x_csr_kernel<<<WB, 256>>>();
    {
        dim3 grid((N_NODES + 127) / 128, D_HID / 128);   // 782 x 8
        gemm1_mma_kernel<<<grid, 256, GT1_SMEM>>>(W1, b1);
    }
    gemm2_kernel<<<296, 256, GEMM2_SMEM>>>(W2);
    spmm_z_csr_kernel<<<WB, 256>>>(b2, out);
}

// round 6
// speedup vs baseline: 3.4147x; 1.9479x over previous
#include <cuda_runtime.h>
#include <cstdint>

#define N_NODES 100000
#define N_EDGES 3200000
#define D_IN 83
#define XP 96
#define D_HID 1024
#define NC 25
#define ZP 32
#define NBLK 391

// ---------------- scratch ----------------
__device__ float g_x[(size_t)N_NODES * XP];
__device__ float g_ax[(size_t)N_NODES * XP];
__device__ float g_z[(size_t)N_NODES * ZP];
__device__ int   g_cnt[N_NODES];
__device__ int   g_rowptr[N_NODES + 1];
__device__ int   g_cur[N_NODES + 1];
__device__ int   g_bsum[NBLK];
__device__ int   g_boff[NBLK];
__device__ int   g_ecol[N_EDGES];
__device__ float g_eval[N_EDGES];

__device__ __forceinline__ float to_tf32(float v) {
    float r;
    asm("cvt.rna.tf32.f32 %0, %1;" : "=f"(r) : "f"(v));
    return r;
}

// ---------------- 1. conv prelude ----------------
__global__ void conv_relu_kernel(const float* __restrict__ feat,
                                 const float* __restrict__ conv_w,
                                 const float* __restrict__ conv_b) {
    __shared__ float srow[D_IN];
    __shared__ float sw[5];
    __shared__ float sb;
    int n = blockIdx.x;
    int t = threadIdx.x;
    if (t < 5) sw[t] = conv_w[t] + conv_w[5 + t] + conv_w[10 + t] + conv_w[15 + t];
    if (t == 5) sb = conv_b[0] + conv_b[1] + conv_b[2] + conv_b[3];
    if (t < D_IN) srow[t] = feat[(size_t)n * D_IN + t];
    __syncthreads();
    float r = 0.f;
    if (t < D_IN) {
        float s = sb;
        #pragma unroll
        for (int k = 0; k < 5; k++) {
            int j = t + k - 2;
            if (j >= 0 && j < D_IN) s += srow[j] * sw[k];
        }
        r = fmaxf(s, 0.f);
    }
    g_x[(size_t)n * XP + t] = r;
}

// ---------------- CSR build ----------------
__global__ void zero_cnt_kernel() {
    int i = blockIdx.x * blockDim.x + threadIdx.x;
    if (i < N_NODES) g_cnt[i] = 0;
}
__global__ void count_kernel(const int* __restrict__ row) {
    int e = blockIdx.x * blockDim.x + threadIdx.x;
    if (e < N_EDGES) atomicAdd(&g_cnt[row[e]], 1);
}
__global__ void scan1_kernel() {
    __shared__ int s[256];
    int t = threadIdx.x;
    int i = blockIdx.x * 256 + t;
    int v = (i < N_NODES) ? g_cnt[i] : 0;
    s[t] = v;
    __syncthreads();
    #pragma unroll
    for (int d = 1; d < 256; d <<= 1) {
        int x = (t >= d) ? s[t - d] : 0;
        __syncthreads();
        s[t] += x;
        __syncthreads();
    }
    if (i < N_NODES) g_rowptr[i + 1] = s[t];
    if (t == 255) g_bsum[blockIdx.x] = s[255];
}
__global__ void scan2_kernel() {
    __shared__ int s[512];
    int t = threadIdx.x;
    s[t] = (t < NBLK) ? g_bsum[t] : 0;
    __syncthreads();
    #pragma unroll
    for (int d = 1; d < 512; d <<= 1) {
        int x = (t >= d) ? s[t - d] : 0;
        __syncthreads();
        s[t] += x;
        __syncthreads();
    }
    if (t < NBLK) g_boff[t] = (t > 0) ? s[t - 1] : 0;
}
__global__ void scan3_kernel() {
    int t = threadIdx.x;
    int i = blockIdx.x * 256 + t;
    if (i < N_NODES) {
        int val = g_rowptr[i + 1] + g_boff[blockIdx.x];
        g_rowptr[i + 1] = val;
        g_cur[i + 1] = val;
    }
    if (i == 0) { g_rowptr[0] = 0; g_cur[0] = 0; }
}
__global__ void scatter_kernel(const float* __restrict__ val,
                               const int* __restrict__ row,
                               const int* __restrict__ col) {
    int e = blockIdx.x * blockDim.x + threadIdx.x;
    if (e < N_EDGES) {
        int r = row[e];
        int pos = atomicAdd(&g_cur[r], 1);
        g_ecol[pos] = col[e];
        g_eval[pos] = val[e];
    }
}

// ---------------- 3. SpMM1 (gather) ----------------
__global__ void spmm_x_csr_kernel() {
    int w = (blockIdx.x * blockDim.x + threadIdx.x) >> 5;
    int lane = threadIdx.x & 31;
    if (w >= N_NODES) return;
    int s = g_rowptr[w], e = g_rowptr[w + 1];
    float a0 = 0.f, a1 = 0.f, a2 = 0.f;
    float b0 = 0.f, b1 = 0.f, b2 = 0.f;
    int j = s;
    for (; j + 1 < e; j += 2) {
        int   c0 = g_ecol[j],   c1 = g_ecol[j + 1];
        float v0 = g_eval[j],   v1 = g_eval[j + 1];
        const float* s0 = g_x + (size_t)c0 * XP;
        const float* s1 = g_x + (size_t)c1 * XP;
        a0 = fmaf(v0, s0[lane],      a0);
        a1 = fmaf(v0, s0[lane + 32], a1);
        a2 = fmaf(v0, s0[lane + 64], a2);
        b0 = fmaf(v1, s1[lane],      b0);
        b1 = fmaf(v1, s1[lane + 32], b1);
        b2 = fmaf(v1, s1[lane + 64], b2);
    }
    if (j < e) {
        int c0 = g_ecol[j]; float v0 = g_eval[j];
        const float* s0 = g_x + (size_t)c0 * XP;
        a0 = fmaf(v0, s0[lane],      a0);
        a1 = fmaf(v0, s0[lane + 32], a1);
        a2 = fmaf(v0, s0[lane + 64], a2);
    }
    float* dst = g_ax + (size_t)w * XP;
    dst[lane]      = a0 + b0;
    dst[lane + 32] = a1 + b1;
    dst[lane + 64] = a2 + b2;
}

// ---------------- 4+5 fused: z = relu(ax @ W1 + b1) @ W2 -------------------
// One CTA per 128-row m-tile. Loop over 8 n-tiles of W1: mma1 (128x128x96),
// bias+relu -> Hs (smem, tf32), mma2 (128x32x128) accumulating z in regs.
// h never touches HBM.
#define AST  100   // As stride   (mod 32 == 4 : conflict-free A-frag reads)
#define B1ST 136   // B1s stride  (mod 32 == 8 : conflict-free B-frag reads)
#define HST  132   // Hs stride   (mod 32 == 4)
#define W2ST 40    // W2s stride  (mod 32 == 8)
#define FUSED_SMEM ((128 * AST + 96 * B1ST + 128 * HST + 128 * W2ST + D_HID) * 4)

__device__ __forceinline__ void mma_tf32_16x8x8(float* d, const uint32_t* a, const uint32_t* b) {
    asm volatile(
        "mma.sync.aligned.m16n8k8.row.col.f32.tf32.tf32.f32 "
        "{%0,%1,%2,%3}, {%4,%5,%6,%7}, {%8,%9}, {%0,%1,%2,%3};"
        : "+f"(d[0]), "+f"(d[1]), "+f"(d[2]), "+f"(d[3])
        : "r"(a[0]), "r"(a[1]), "r"(a[2]), "r"(a[3]), "r"(b[0]), "r"(b[1]));
}

__global__ __launch_bounds__(256, 1) void fused_gemm_kernel(const float* __restrict__ W1,
                                                            const float* __restrict__ b1,
                                                            const float* __restrict__ W2) {
    extern __shared__ float sm[];
    float* As  = sm;                      // [128][100]
    float* B1s = As + 128 * AST;          // [96][136]
    float* Hs  = B1s + 96 * B1ST;         // [128][132]
    float* W2s = Hs + 128 * HST;          // [128][40]
    float* sB1 = W2s + 128 * W2ST;        // [1024]

    int t = threadIdx.x;
    int wid = t >> 5, lane = t & 31;
    int g = lane >> 2, tg = lane & 3;
    int m0 = blockIdx.x * 128;

    // stage A once (tf32-rounded, zero-padded)
    #pragma unroll
    for (int it = 0; it < 12; it++) {
        int flat = it * 256 + t;
        int rr = flat / 24, q = flat % 24;
        float4 v = make_float4(0.f, 0.f, 0.f, 0.f);
        int gr = m0 + rr;
        if (gr < N_NODES) v = *(const float4*)&g_ax[(size_t)gr * XP + q * 4];
        v.x = to_tf32(v.x); v.y = to_tf32(v.y); v.z = to_tf32(v.z); v.w = to_tf32(v.w);
        *(float4*)&As[rr * AST + q * 4] = v;
    }
    // full bias vector once
    for (int i = t; i < D_HID; i += 256) sB1[i] = b1[i];

    // mma1 warp coords (2x4 warps, 64x32 each); mma2: warp owns 16 rows
    int wm = (wid & 1) * 64;
    int wn = (wid >> 1) * 32;

    float accz[4][4];
    #pragma unroll
    for (int ct = 0; ct < 4; ct++)
        #pragma unroll
        for (int i = 0; i < 4; i++) accz[ct][i] = 0.f;

    for (int nt = 0; nt < 8; nt++) {
        int n0 = nt * 128;
        // stage W1 n-tile: B1s[k][n] (k<83 else 0)
        #pragma unroll
        for (int it = 0; it < 12; it++) {
            int flat = it * 256 + t;
            int k = flat >> 5, n4 = flat & 31;
            float4 v = make_float4(0.f, 0.f, 0.f, 0.f);
            if (k < D_IN) {
                v = *(const float4*)&W1[(size_t)k * D_HID + n0 + n4 * 4];
                v.x = to_tf32(v.x); v.y = to_tf32(v.y); v.z = to_tf32(v.z); v.w = to_tf32(v.w);
            }
            *(float4*)&B1s[k * B1ST + n4 * 4] = v;
        }
        // stage W2 k-slice: W2s[kk][c], c<25 else 0
        #pragma unroll
        for (int it = 0; it < 16; it++) {
            int idx = it * 256 + t;
            int kk = idx >> 5, c = idx & 31;
            float v = (c < NC) ? to_tf32(W2[(size_t)(n0 + kk) * NC + c]) : 0.f;
            W2s[kk * W2ST + c] = v;
        }
        __syncthreads();

        // ---- mma1: acc1 = As @ B1s ----
        float acc1[4][4][4];
        #pragma unroll
        for (int mt = 0; mt < 4; mt++)
            #pragma unroll
            for (int n2 = 0; n2 < 4; n2++)
                #pragma unroll
                for (int i = 0; i < 4; i++) acc1[mt][n2][i] = 0.f;

        #pragma unroll
        for (int ks = 0; ks < 12; ks++) {
            int k0 = ks * 8;
            uint32_t a[4][4];
            #pragma unroll
            for (int mt = 0; mt < 4; mt++) {
                const float* ap = &As[(wm + mt * 16 + g) * AST + k0 + tg];
                a[mt][0] = __float_as_uint(ap[0]);
                a[mt][1] = __float_as_uint(ap[8 * AST]);
                a[mt][2] = __float_as_uint(ap[4]);
                a[mt][3] = __float_as_uint(ap[8 * AST + 4]);
            }
            uint32_t b[4][2];
            #pragma unroll
            for (int n2 = 0; n2 < 4; n2++) {
                const float* bp = &B1s[(k0 + tg) * B1ST + wn + n2 * 8 + g];
                b[n2][0] = __float_as_uint(bp[0]);
                b[n2][1] = __float_as_uint(bp[4 * B1ST]);
            }
            #pragma unroll
            for (int mt = 0; mt < 4; mt++)
                #pragma unroll
                for (int n2 = 0; n2 < 4; n2++)
                    mma_tf32_16x8x8(acc1[mt][n2], a[mt], b[n2]);
        }

        // ---- h = relu(acc1 + bias), tf32-round, to Hs ----
        #pragma unroll
        for (int n2 = 0; n2 < 4; n2++) {
            int col = wn + n2 * 8 + tg * 2;
            float bz0 = sB1[n0 + col], bz1 = sB1[n0 + col + 1];
            #pragma unroll
            for (int mt = 0; mt < 4; mt++) {
                int r0 = wm + mt * 16 + g;
                Hs[r0 * HST + col]           = to_tf32(fmaxf(acc1[mt][n2][0] + bz0, 0.f));
                Hs[r0 * HST + col + 1]       = to_tf32(fmaxf(acc1[mt][n2][1] + bz1, 0.f));
                Hs[(r0 + 8) * HST + col]     = to_tf32(fmaxf(acc1[mt][n2][2] + bz0, 0.f));
                Hs[(r0 + 8) * HST + col + 1] = to_tf32(fmaxf(acc1[mt][n2][3] + bz1, 0.f));
            }
        }
        __syncthreads();

        // ---- mma2: accz += Hs @ W2s (warp rows wid*16..wid*16+15) ----
        #pragma unroll
        for (int ks = 0; ks < 16; ks++) {
            int k0 = ks * 8;
            uint32_t a[4];
            const float* ap = &Hs[(wid * 16 + g) * HST + k0 + tg];
            a[0] = __float_as_uint(ap[0]);
            a[1] = __float_as_uint(ap[8 * HST]);
            a[2] = __float_as_uint(ap[4]);
            a[3] = __float_as_uint(ap[8 * HST + 4]);
            #pragma unroll
            for (int ct = 0; ct < 4; ct++) {
                uint32_t b[2];
                const float* bp = &W2s[(k0 + tg) * W2ST + ct * 8 + g];
                b[0] = __float_as_uint(bp[0]);
                b[1] = __float_as_uint(bp[4 * W2ST]);
                mma_tf32_16x8x8(accz[ct], a, b);
            }
        }
        __syncthreads();   // protect B1s/W2s/Hs before next iteration's staging
    }

    // ---- store z ----
    #pragma unroll
    for (int ct = 0; ct < 4; ct++) {
        int col = ct * 8 + tg * 2;
        int r0 = m0 + wid * 16 + g;
        if (r0 < N_NODES) {
            float2 o = make_float2(accz[ct][0], accz[ct][1]);
            *(float2*)&g_z[(size_t)r0 * ZP + col] = o;
        }
        int r1 = r0 + 8;
        if (r1 < N_NODES) {
            float2 o = make_float2(accz[ct][2], accz[ct][3]);
            *(float2*)&g_z[(size_t)r1 * ZP + col] = o;
        }
    }
}

// ---------------- 7. SpMM2 (gather) ----------------
__global__ void spmm_z_csr_kernel(const float* __restrict__ b2,
                                  float* __restrict__ out) {
    int w = (blockIdx.x * blockDim.x + threadIdx.x) >> 5;
    int lane = threadIdx.x & 31;
    if (w >= N_NODES) return;
    int s = g_rowptr[w], e = g_rowptr[w + 1];
    float acc = 0.f, accb = 0.f;
    int j = s;
    for (; j + 1 < e; j += 2) {
        int   c0 = g_ecol[j],   c1 = g_ecol[j + 1];
        float v0 = g_eval[j],   v1 = g_eval[j + 1];
        acc  = fmaf(v0, g_z[(size_t)c0 * ZP + lane], acc);
        accb = fmaf(v1, g_z[(size_t)c1 * ZP + lane], accb);
    }
    if (j < e) {
        int c0 = g_ecol[j]; float v0 = g_eval[j];
        acc = fmaf(v0, g_z[(size_t)c0 * ZP + lane], acc);
    }
    if (lane < NC)
        out[(size_t)w * NC + lane] = acc + accb + b2[lane];
}

// ---------------- launch ----------------
extern "C" void kernel_launch(void* const* d_in, const int* in_sizes, int n_in,
                              void* d_out, int out_size) {
    const float* feature = (const float*)d_in[0];
    const float* conv_w  = (const float*)d_in[1];
    const float* conv_b  = (const float*)d_in[2];
    const float* W1      = (const float*)d_in[3];
    const float* b1      = (const float*)d_in[4];
    const float* W2      = (const float*)d_in[5];
    const float* b2      = (const float*)d_in[6];
    const float* adj_val = (const float*)d_in[7];
    const int*   e_row   = (const int*)d_in[8];
    const int*   e_col   = (const int*)d_in[9];
    float* out = (float*)d_out;

    cudaFuncSetAttribute(fused_gemm_kernel, cudaFuncAttributeMaxDynamicSharedMemorySize, FUSED_SMEM);

    const int EB = (N_EDGES + 255) / 256;
    const int WB = (N_NODES * 32 + 255) / 256;

    conv_relu_kernel<<<N_NODES, 96>>>(feature, conv_w, conv_b);
    zero_cnt_kernel<<<NBLK, 256>>>();
    count_kernel<<<EB, 256>>>(e_row);
    scan1_kernel<<<NBLK, 256>>>();
    scan2_kernel<<<1, 512>>>();
    scan3_kernel<<<NBLK, 256>>>();
    scatter_kernel<<<EB, 256>>>(adj_val, e_row, e_col);
    spmm_x_csr_kernel<<<WB, 256>>>();
    fused_gemm_kernel<<<(N_NODES + 127) / 128, 256, FUSED_SMEM>>>(W1, b1, W2);
    spmm_z_csr_kernel<<<WB, 256>>>(b2, out);
}

// round 7
// speedup vs baseline: 3.5161x; 1.0297x over previous
#include <cuda_runtime.h>
#include <cuda_fp16.h>
#include <cstdint>

#define N_NODES 100000
#define N_EDGES 3200000
#define D_IN 83
#define XP 96          // x row stride in halves (192B)
#define D_HID 1024
#define NC 25
#define ZP 32          // z row stride in halves (64B)
#define NBLK 391

// ---------------- scratch ----------------
__device__ __half g_xh[(size_t)N_NODES * XP];   // conv output (fp16)
__device__ float  g_ax[(size_t)N_NODES * XP];   // A @ x (fp32)
__device__ __half g_zh[(size_t)N_NODES * ZP];   // h @ W2 (fp16)
__device__ int    g_cnt[N_NODES];
__device__ int    g_rowptr[N_NODES + 1];
__device__ int    g_cur[N_NODES + 1];
__device__ int    g_bsum[NBLK];
__device__ int    g_boff[NBLK];
__device__ int2   g_edge[N_EDGES];              // (col, val bits)

__device__ __forceinline__ float to_tf32(float v) {
    float r;
    asm("cvt.rna.tf32.f32 %0, %1;" : "=f"(r) : "f"(v));
    return r;
}

// ---------------- 1. conv prelude (fp16 out) ----------------
__global__ void conv_relu_kernel(const float* __restrict__ feat,
                                 const float* __restrict__ conv_w,
                                 const float* __restrict__ conv_b) {
    __shared__ float srow[D_IN];
    __shared__ float sw[5];
    __shared__ float sb;
    int n = blockIdx.x;
    int t = threadIdx.x;
    if (t < 5) sw[t] = conv_w[t] + conv_w[5 + t] + conv_w[10 + t] + conv_w[15 + t];
    if (t == 5) sb = conv_b[0] + conv_b[1] + conv_b[2] + conv_b[3];
    if (t < D_IN) srow[t] = feat[(size_t)n * D_IN + t];
    __syncthreads();
    float r = 0.f;
    if (t < D_IN) {
        float s = sb;
        #pragma unroll
        for (int k = 0; k < 5; k++) {
            int j = t + k - 2;
            if (j >= 0 && j < D_IN) s += srow[j] * sw[k];
        }
        r = fmaxf(s, 0.f);
    }
    g_xh[(size_t)n * XP + t] = __float2half_rn(r);
}

// ---------------- CSR build ----------------
__global__ void zero_cnt_kernel() {
    int i = blockIdx.x * blockDim.x + threadIdx.x;
    if (i < N_NODES) g_cnt[i] = 0;
}
__global__ void count_kernel(const int* __restrict__ row) {
    int e = blockIdx.x * blockDim.x + threadIdx.x;
    if (e < N_EDGES) atomicAdd(&g_cnt[row[e]], 1);
}
__global__ void scan1_kernel() {
    __shared__ int s[256];
    int t = threadIdx.x;
    int i = blockIdx.x * 256 + t;
    int v = (i < N_NODES) ? g_cnt[i] : 0;
    s[t] = v;
    __syncthreads();
    #pragma unroll
    for (int d = 1; d < 256; d <<= 1) {
        int x = (t >= d) ? s[t - d] : 0;
        __syncthreads();
        s[t] += x;
        __syncthreads();
    }
    if (i < N_NODES) g_rowptr[i + 1] = s[t];
    if (t == 255) g_bsum[blockIdx.x] = s[255];
}
__global__ void scan2_kernel() {
    __shared__ int s[512];
    int t = threadIdx.x;
    s[t] = (t < NBLK) ? g_bsum[t] : 0;
    __syncthreads();
    #pragma unroll
    for (int d = 1; d < 512; d <<= 1) {
        int x = (t >= d) ? s[t - d] : 0;
        __syncthreads();
        s[t] += x;
        __syncthreads();
    }
    if (t < NBLK) g_boff[t] = (t > 0) ? s[t - 1] : 0;
}
__global__ void scan3_kernel() {
    int t = threadIdx.x;
    int i = blockIdx.x * 256 + t;
    if (i < N_NODES) {
        int val = g_rowptr[i + 1] + g_boff[blockIdx.x];
        g_rowptr[i + 1] = val;
        g_cur[i + 1] = val;
    }
    if (i == 0) { g_rowptr[0] = 0; g_cur[0] = 0; }
}
__global__ void scatter_kernel(const float* __restrict__ val,
                               const int* __restrict__ row,
                               const int* __restrict__ col) {
    int e = blockIdx.x * blockDim.x + threadIdx.x;
    if (e < N_EDGES) {
        int r = row[e];
        int pos = atomicAdd(&g_cur[r], 1);
        g_edge[pos] = make_int2(col[e], __float_as_int(val[e]));
    }
}

// ---------------- 3. SpMM1 (gather, fp16 x, fp32 accum) ----------------
__global__ void spmm_x_csr_kernel() {
    int w = (blockIdx.x * blockDim.x + threadIdx.x) >> 5;
    int lane = threadIdx.x & 31;
    if (w >= N_NODES) return;
    int s = g_rowptr[w], e = g_rowptr[w + 1];
    float2 a0 = make_float2(0.f, 0.f), a1 = make_float2(0.f, 0.f);
    float2 b0 = make_float2(0.f, 0.f), b1 = make_float2(0.f, 0.f);
    int j = s;
    for (; j + 1 < e; j += 2) {
        int2 e0 = g_edge[j], e1 = g_edge[j + 1];
        float v0 = __int_as_float(e0.y), v1 = __int_as_float(e1.y);
        const __half2* s0 = (const __half2*)(g_xh + (size_t)e0.x * XP);
        const __half2* s1 = (const __half2*)(g_xh + (size_t)e1.x * XP);
        float2 f0 = __half22float2(s0[lane]);
        float2 f1 = __half22float2(s1[lane]);
        a0.x = fmaf(v0, f0.x, a0.x); a0.y = fmaf(v0, f0.y, a0.y);
        b0.x = fmaf(v1, f1.x, b0.x); b0.y = fmaf(v1, f1.y, b0.y);
        if (lane < 16) {
            float2 g0 = __half22float2(s0[32 + lane]);
            float2 g1 = __half22float2(s1[32 + lane]);
            a1.x = fmaf(v0, g0.x, a1.x); a1.y = fmaf(v0, g0.y, a1.y);
            b1.x = fmaf(v1, g1.x, b1.x); b1.y = fmaf(v1, g1.y, b1.y);
        }
    }
    if (j < e) {
        int2 e0 = g_edge[j];
        float v0 = __int_as_float(e0.y);
        const __half2* s0 = (const __half2*)(g_xh + (size_t)e0.x * XP);
        float2 f0 = __half22float2(s0[lane]);
        a0.x = fmaf(v0, f0.x, a0.x); a0.y = fmaf(v0, f0.y, a0.y);
        if (lane < 16) {
            float2 g0 = __half22float2(s0[32 + lane]);
            a1.x = fmaf(v0, g0.x, a1.x); a1.y = fmaf(v0, g0.y, a1.y);
        }
    }
    float* dst = g_ax + (size_t)w * XP;
    *(float2*)&dst[lane * 2] = make_float2(a0.x + b0.x, a0.y + b0.y);
    if (lane < 16)
        *(float2*)&dst[64 + lane * 2] = make_float2(a1.x + b1.x, a1.y + b1.y);
}

// ---------------- 4+5 fused: z = relu(ax @ W1 + b1) @ W2 (z in fp16) -------
#define AST  100
#define B1ST 136
#define HST  132
#define W2ST 40
#define FUSED_SMEM ((128 * AST + 96 * B1ST + 128 * HST + 128 * W2ST + D_HID) * 4)

__device__ __forceinline__ void mma_tf32_16x8x8(float* d, const uint32_t* a, const uint32_t* b) {
    asm volatile(
        "mma.sync.aligned.m16n8k8.row.col.f32.tf32.tf32.f32 "
        "{%0,%1,%2,%3}, {%4,%5,%6,%7}, {%8,%9}, {%0,%1,%2,%3};"
        : "+f"(d[0]), "+f"(d[1]), "+f"(d[2]), "+f"(d[3])
        : "r"(a[0]), "r"(a[1]), "r"(a[2]), "r"(a[3]), "r"(b[0]), "r"(b[1]));
}

__global__ __launch_bounds__(256, 1) void fused_gemm_kernel(const float* __restrict__ W1,
                                                            const float* __restrict__ b1,
                                                            const float* __restrict__ W2) {
    extern __shared__ float sm[];
    float* As  = sm;                      // [128][100]
    float* B1s = As + 128 * AST;          // [96][136]
    float* Hs  = B1s + 96 * B1ST;         // [128][132]
    float* W2s = Hs + 128 * HST;          // [128][40]
    float* sB1 = W2s + 128 * W2ST;        // [1024]

    int t = threadIdx.x;
    int wid = t >> 5, lane = t & 31;
    int g = lane >> 2, tg = lane & 3;
    int m0 = blockIdx.x * 128;

    #pragma unroll
    for (int it = 0; it < 12; it++) {
        int flat = it * 256 + t;
        int rr = flat / 24, q = flat % 24;
        float4 v = make_float4(0.f, 0.f, 0.f, 0.f);
        int gr = m0 + rr;
        if (gr < N_NODES) v = *(const float4*)&g_ax[(size_t)gr * XP + q * 4];
        v.x = to_tf32(v.x); v.y = to_tf32(v.y); v.z = to_tf32(v.z); v.w = to_tf32(v.w);
        *(float4*)&As[rr * AST + q * 4] = v;
    }
    for (int i = t; i < D_HID; i += 256) sB1[i] = b1[i];

    int wm = (wid & 1) * 64;
    int wn = (wid >> 1) * 32;

    float accz[4][4];
    #pragma unroll
    for (int ct = 0; ct < 4; ct++)
        #pragma unroll
        for (int i = 0; i < 4; i++) accz[ct][i] = 0.f;

    for (int nt = 0; nt < 8; nt++) {
        int n0 = nt * 128;
        #pragma unroll
        for (int it = 0; it < 12; it++) {
            int flat = it * 256 + t;
            int k = flat >> 5, n4 = flat & 31;
            float4 v = make_float4(0.f, 0.f, 0.f, 0.f);
            if (k < D_IN) {
                v = *(const float4*)&W1[(size_t)k * D_HID + n0 + n4 * 4];
                v.x = to_tf32(v.x); v.y = to_tf32(v.y); v.z = to_tf32(v.z); v.w = to_tf32(v.w);
            }
            *(float4*)&B1s[k * B1ST + n4 * 4] = v;
        }
        #pragma unroll
        for (int it = 0; it < 16; it++) {
            int idx = it * 256 + t;
            int kk = idx >> 5, c = idx & 31;
            float v = (c < NC) ? to_tf32(W2[(size_t)(n0 + kk) * NC + c]) : 0.f;
            W2s[kk * W2ST + c] = v;
        }
        __syncthreads();

        float acc1[4][4][4];
        #pragma unroll
        for (int mt = 0; mt < 4; mt++)
            #pragma unroll
            for (int n2 = 0; n2 < 4; n2++)
                #pragma unroll
                for (int i = 0; i < 4; i++) acc1[mt][n2][i] = 0.f;

        #pragma unroll
        for (int ks = 0; ks < 12; ks++) {
            int k0 = ks * 8;
            uint32_t a[4][4];
            #pragma unroll
            for (int mt = 0; mt < 4; mt++) {
                const float* ap = &As[(wm + mt * 16 + g) * AST + k0 + tg];
                a[mt][0] = __float_as_uint(ap[0]);
                a[mt][1] = __float_as_uint(ap[8 * AST]);
                a[mt][2] = __float_as_uint(ap[4]);
                a[mt][3] = __float_as_uint(ap[8 * AST + 4]);
            }
            uint32_t b[4][2];
            #pragma unroll
            for (int n2 = 0; n2 < 4; n2++) {
                const float* bp = &B1s[(k0 + tg) * B1ST + wn + n2 * 8 + g];
                b[n2][0] = __float_as_uint(bp[0]);
                b[n2][1] = __float_as_uint(bp[4 * B1ST]);
            }
            #pragma unroll
            for (int mt = 0; mt < 4; mt++)
                #pragma unroll
                for (int n2 = 0; n2 < 4; n2++)
                    mma_tf32_16x8x8(acc1[mt][n2], a[mt], b[n2]);
        }

        #pragma unroll
        for (int n2 = 0; n2 < 4; n2++) {
            int col = wn + n2 * 8 + tg * 2;
            float bz0 = sB1[n0 + col], bz1 = sB1[n0 + col + 1];
            #pragma unroll
            for (int mt = 0; mt < 4; mt++) {
                int r0 = wm + mt * 16 + g;
                Hs[r0 * HST + col]           = to_tf32(fmaxf(acc1[mt][n2][0] + bz0, 0.f));
                Hs[r0 * HST + col + 1]       = to_tf32(fmaxf(acc1[mt][n2][1] + bz1, 0.f));
                Hs[(r0 + 8) * HST + col]     = to_tf32(fmaxf(acc1[mt][n2][2] + bz0, 0.f));
                Hs[(r0 + 8) * HST + col + 1] = to_tf32(fmaxf(acc1[mt][n2][3] + bz1, 0.f));
            }
        }
        __syncthreads();

        #pragma unroll
        for (int ks = 0; ks < 16; ks++) {
            int k0 = ks * 8;
            uint32_t a[4];
            const float* ap = &Hs[(wid * 16 + g) * HST + k0 + tg];
            a[0] = __float_as_uint(ap[0]);
            a[1] = __float_as_uint(ap[8 * HST]);
            a[2] = __float_as_uint(ap[4]);
            a[3] = __float_as_uint(ap[8 * HST + 4]);
            #pragma unroll
            for (int ct = 0; ct < 4; ct++) {
                uint32_t b[2];
                const float* bp = &W2s[(k0 + tg) * W2ST + ct * 8 + g];
                b[0] = __float_as_uint(bp[0]);
                b[1] = __float_as_uint(bp[4 * W2ST]);
                mma_tf32_16x8x8(accz[ct], a, b);
            }
        }
        __syncthreads();
    }

    // store z as fp16 (half2 per col pair)
    #pragma unroll
    for (int ct = 0; ct < 4; ct++) {
        int col = ct * 8 + tg * 2;
        int r0 = m0 + wid * 16 + g;
        if (r0 < N_NODES) {
            __half2 o = __floats2half2_rn(accz[ct][0], accz[ct][1]);
            *(__half2*)&g_zh[(size_t)r0 * ZP + col] = o;
        }
        int r1 = r0 + 8;
        if (r1 < N_NODES) {
            __half2 o = __floats2half2_rn(accz[ct][2], accz[ct][3]);
            *(__half2*)&g_zh[(size_t)r1 * ZP + col] = o;
        }
    }
}

// ---------------- 7. SpMM2 (gather, fp16 z, fp32 accum) ----------------
__global__ void spmm_z_csr_kernel(const float* __restrict__ b2,
                                  float* __restrict__ out) {
    int w = (blockIdx.x * blockDim.x + threadIdx.x) >> 5;
    int lane = threadIdx.x & 31;
    if (w >= N_NODES) return;
    int s = g_rowptr[w], e = g_rowptr[w + 1];
    float2 acc = make_float2(0.f, 0.f), accb = make_float2(0.f, 0.f);
    int j = s;
    for (; j + 1 < e; j += 2) {
        int2 e0 = g_edge[j], e1 = g_edge[j + 1];
        float v0 = __int_as_float(e0.y), v1 = __int_as_float(e1.y);
        if (lane < 13) {
            float2 f0 = __half22float2(((const __half2*)(g_zh + (size_t)e0.x * ZP))[lane]);
            float2 f1 = __half22float2(((const __half2*)(g_zh + (size_t)e1.x * ZP))[lane]);
            acc.x  = fmaf(v0, f0.x, acc.x);  acc.y  = fmaf(v0, f0.y, acc.y);
            accb.x = fmaf(v1, f1.x, accb.x); accb.y = fmaf(v1, f1.y, accb.y);
        }
    }
    if (j < e) {
        int2 e0 = g_edge[j];
        float v0 = __int_as_float(e0.y);
        if (lane < 13) {
            float2 f0 = __half22float2(((const __half2*)(g_zh + (size_t)e0.x * ZP))[lane]);
            acc.x = fmaf(v0, f0.x, acc.x); acc.y = fmaf(v0, f0.y, acc.y);
        }
    }
    if (lane < 13) {
        int c0 = lane * 2;
        out[(size_t)w * NC + c0] = acc.x + accb.x + b2[c0];
        if (c0 + 1 < NC)
            out[(size_t)w * NC + c0 + 1] = acc.y + accb.y + b2[c0 + 1];
    }
}

// ---------------- launch ----------------
extern "C" void kernel_launch(void* const* d_in, const int* in_sizes, int n_in,
                              void* d_out, int out_size) {
    const float* feature = (const float*)d_in[0];
    const float* conv_w  = (const float*)d_in[1];
    const float* conv_b  = (const float*)d_in[2];
    const float* W1      = (const float*)d_in[3];
    const float* b1      = (const float*)d_in[4];
    const float* W2      = (const float*)d_in[5];
    const float* b2      = (const float*)d_in[6];
    const float* adj_val = (const float*)d_in[7];
    const int*   e_row   = (const int*)d_in[8];
    const int*   e_col   = (const int*)d_in[9];
    float* out = (float*)d_out;

    cudaFuncSetAttribute(fused_gemm_kernel, cudaFuncAttributeMaxDynamicSharedMemorySize, FUSED_SMEM);

    const int EB = (N_EDGES + 255) / 256;
    const int WB = (N_NODES * 32 + 255) / 256;

    conv_relu_kernel<<<N_NODES, 96>>>(feature, conv_w, conv_b);
    zero_cnt_kernel<<<NBLK, 256>>>();
    count_kernel<<<EB, 256>>>(e_row);
    scan1_kernel<<<NBLK, 256>>>();
    scan2_kernel<<<1, 512>>>();
    scan3_kernel<<<NBLK, 256>>>();
    scatter_kernel<<<EB, 256>>>(adj_val, e_row, e_col);
    spmm_x_csr_kernel<<<WB, 256>>>();
    fused_gemm_kernel<<<(N_NODES + 127) / 128, 256, FUSED_SMEM>>>(W1, b1, W2);
    spmm_z_csr_kernel<<<WB, 256>>>(b2, out);
}